// round 15
// baseline (speedup 1.0000x reference)
#include <cuda_runtime.h>
#include <cuda_bf16.h>
#include <stdint.h>
#include <cstdint>
#include <math.h>

typedef unsigned int u32;

#define D_DIM 512
#define NB 4096
#define NK 16384
#define BETA 5.5f
#define ALPHA 0.5f
#define NSPLIT 4

// bf16 scratch
__device__ __nv_bfloat16 g_qh[(size_t)NB * D_DIM];    // normalized queries (4 MB)
__device__ __nv_bfloat16 g_ckh[(size_t)NK * D_DIM];   // normalized keys    (16 MB)
__device__ __nv_bfloat16 g_aff[(size_t)NB * NK];      // affinity           (128 MB)
__device__ float g_part[(size_t)NSPLIT * NB * D_DIM]; // split-K partials   (32 MB)

// ---------------------------------------------------------------------------
// PTX helpers
// ---------------------------------------------------------------------------
__device__ __forceinline__ void cp16(u32 saddr, const void* g) {
    asm volatile("cp.async.cg.shared.global [%0], [%1], 16;\n" :: "r"(saddr), "l"(g));
}
__device__ __forceinline__ void cp_commit() { asm volatile("cp.async.commit_group;\n"); }
__device__ __forceinline__ void cp_wait_2() { asm volatile("cp.async.wait_group 2;\n"); }

__device__ __forceinline__ void ldsm_x4(u32* r, u32 addr) {
    asm volatile("ldmatrix.sync.aligned.m8n8.x4.shared.b16 {%0,%1,%2,%3}, [%4];\n"
        : "=r"(r[0]), "=r"(r[1]), "=r"(r[2]), "=r"(r[3]) : "r"(addr));
}
__device__ __forceinline__ void ldsm_x4_t(u32* r, u32 addr) {
    asm volatile("ldmatrix.sync.aligned.m8n8.x4.trans.shared.b16 {%0,%1,%2,%3}, [%4];\n"
        : "=r"(r[0]), "=r"(r[1]), "=r"(r[2]), "=r"(r[3]) : "r"(addr));
}
__device__ __forceinline__ void mma16816(float* c, const u32* a, u32 b0, u32 b1) {
    asm volatile(
        "mma.sync.aligned.m16n8k16.row.col.f32.bf16.bf16.f32 "
        "{%0,%1,%2,%3}, {%4,%5,%6,%7}, {%8,%9}, {%0,%1,%2,%3};\n"
        : "+f"(c[0]), "+f"(c[1]), "+f"(c[2]), "+f"(c[3])
        : "r"(a[0]), "r"(a[1]), "r"(a[2]), "r"(a[3]), "r"(b0), "r"(b1));
}

// ---------------------------------------------------------------------------
// Row L2-normalization -> bf16. One warp per 512-float row.
// ---------------------------------------------------------------------------
__global__ void __launch_bounds__(256) norm_rows(const float* __restrict__ src,
                                                 int rows, int dst_sel) {
    int w = (blockIdx.x * blockDim.x + threadIdx.x) >> 5;
    if (w >= rows) return;
    int lane = threadIdx.x & 31;
    __nv_bfloat16* dst = dst_sel ? g_ckh : g_qh;

    const float4* s = (const float4*)(src + (size_t)w * D_DIM);
    float4 v[4];
    float ss = 0.f;
#pragma unroll
    for (int i = 0; i < 4; i++) {
        v[i] = s[lane + 32 * i];
        ss += v[i].x * v[i].x + v[i].y * v[i].y + v[i].z * v[i].z + v[i].w * v[i].w;
    }
#pragma unroll
    for (int o = 16; o; o >>= 1) {
        ss += __shfl_xor_sync(0xffffffffu, ss, o);
    }
    float inv = 1.0f / fmaxf(sqrtf(ss), 1e-12f);

    uint2* d = (uint2*)(dst + (size_t)w * D_DIM);
#pragma unroll
    for (int i = 0; i < 4; i++) {
        __nv_bfloat162 lo = __floats2bfloat162_rn(v[i].x * inv, v[i].y * inv);
        __nv_bfloat162 hi = __floats2bfloat162_rn(v[i].z * inv, v[i].w * inv);
        uint2 u;
        u.x = *(u32*)&lo;
        u.y = *(u32*)&hi;
        d[lane + 32 * i] = u;
    }
}

// ---------------------------------------------------------------------------
// GEMM1: Aff[b][n] = bf16( exp(BETA * dot(qh[b], ckh[n]) - BETA) )
// 128x128x32 tiles, 8 warps (64x32 warp tile), 4-stage cp.async ring,
// pointer-induction loads, one barrier per k-iter.
// ---------------------------------------------------------------------------
#define G1_ASZ 10240            // A (or B) bytes per stage
#define G1_STG (2 * G1_ASZ)
#define G1_SMEM (4 * G1_STG)    // 81920

__global__ void __launch_bounds__(256) gemm1_kernel() {
    extern __shared__ __align__(16) char sm1[];
    const int tid = threadIdx.x;
    const int warp = tid >> 5;
    const int lane = tid & 31;
    const int m0 = blockIdx.y * 128;
    const int n0 = blockIdx.x * 128;
    const int wm = (warp >> 2) * 64;
    const int wn = (warp & 3) * 32;
    const u32 smb = (u32)__cvta_generic_to_shared(sm1);

    // per-thread load slots: chunks tid and tid+256 over 128 rows x 4 chunks
    const int r0 = tid >> 2, c0 = tid & 3;
    const int r1 = (tid + 256) >> 2, c1 = (tid + 256) & 3;
    const u32 sA0 = (u32)(r0 * 80 + c0 * 16);
    const u32 sA1 = (u32)(r1 * 80 + c1 * 16);
    const char* gA0 = (const char*)g_qh + ((size_t)(m0 + r0) * D_DIM + c0 * 8) * 2;
    const char* gA1 = (const char*)g_qh + ((size_t)(m0 + r1) * D_DIM + c1 * 8) * 2;
    const char* gB0 = (const char*)g_ckh + ((size_t)(n0 + r0) * D_DIM + c0 * 8) * 2;
    const char* gB1 = (const char*)g_ckh + ((size_t)(n0 + r1) * D_DIM + c1 * 8) * 2;

    float acc[4][4][4] = {};

    // prologue: stages 0,1,2
#pragma unroll
    for (int p = 0; p < 3; p++) {
        u32 Ab = smb + p * G1_STG;
        cp16(Ab + sA0, gA0); cp16(Ab + sA1, gA1);
        cp16(Ab + G1_ASZ + sA0, gB0); cp16(Ab + G1_ASZ + sA1, gB1);
        cp_commit();
        gA0 += 64; gA1 += 64; gB0 += 64; gB1 += 64;
    }

    const int NT = D_DIM / 32;  // 16
#pragma unroll 4
    for (int kt = 0; kt < NT; kt++) {
        cp_wait_2();
        __syncthreads();
        if (kt + 3 < NT) {
            u32 Ab = smb + ((kt + 3) & 3) * G1_STG;
            cp16(Ab + sA0, gA0); cp16(Ab + sA1, gA1);
            cp16(Ab + G1_ASZ + sA0, gB0); cp16(Ab + G1_ASZ + sA1, gB1);
            cp_commit();
            gA0 += 64; gA1 += 64; gB0 += 64; gB1 += 64;
        } else {
            cp_commit();   // empty group keeps wait-count arithmetic uniform
        }

        u32 Ab = smb + (kt & 3) * G1_STG;
        u32 Bb = Ab + G1_ASZ;
#pragma unroll
        for (int ks = 0; ks < 2; ks++) {
            u32 a[4][4];
            u32 b[2][4];
#pragma unroll
            for (int mi = 0; mi < 4; mi++) {
                ldsm_x4(a[mi], Ab + (wm + mi * 16 + (lane & 15)) * 80 + ks * 32 + (lane >> 4) * 16);
            }
#pragma unroll
            for (int j = 0; j < 2; j++) {
                ldsm_x4(b[j], Bb + (wn + j * 16 + (lane & 15)) * 80 + ks * 32 + (lane >> 4) * 16);
            }
#pragma unroll
            for (int mi = 0; mi < 4; mi++) {
#pragma unroll
                for (int j = 0; j < 2; j++) {
                    mma16816(acc[mi][j * 2 + 0], a[mi], b[j][0], b[j][2]);
                    mma16816(acc[mi][j * 2 + 1], a[mi], b[j][1], b[j][3]);
                }
            }
        }
    }

    // Epilogue: exp + bf16 store
#pragma unroll
    for (int mi = 0; mi < 4; mi++) {
#pragma unroll
        for (int ni = 0; ni < 4; ni++) {
            int col = n0 + wn + ni * 8 + (lane & 3) * 2;
#pragma unroll
            for (int h = 0; h < 2; h++) {
                int row = m0 + wm + mi * 16 + (lane >> 2) + h * 8;
                float e0 = __expf(fmaf(BETA, acc[mi][ni][2 * h + 0], -BETA));
                float e1 = __expf(fmaf(BETA, acc[mi][ni][2 * h + 1], -BETA));
                __nv_bfloat162 v = __floats2bfloat162_rn(e0, e1);
                *(u32*)(&g_aff[(size_t)row * NK + col]) = *(u32*)&v;
            }
        }
    }
}

// ---------------------------------------------------------------------------
// GEMM2 (split-K x4): Part[z][b][d] = sum_{n in split z} Aff[b][n] * ckh[n][d]
// 64x128 tiles, 8 warps (32x32 warp tile), 4-stage ring, grid.z = NSPLIT,
// pointer-induction loads, one barrier per k-iter. launch_bounds(256,4).
// ---------------------------------------------------------------------------
#define G2_ASZ 5120
#define G2_BSZ 8704
#define G2_STG (G2_ASZ + G2_BSZ)   // 13824
#define G2_SMEM (4 * G2_STG)       // 55296

__global__ void __launch_bounds__(256, 4) gemm2_kernel() {
    extern __shared__ __align__(16) char sm2[];
    const int tid = threadIdx.x;
    const int warp = tid >> 5;
    const int lane = tid & 31;
    const int m0 = blockIdx.y * 64;
    const int n0 = blockIdx.x * 128;
    const int split = blockIdx.z;
    const int kt0 = split * (NK / NSPLIT / 32);
    const u32 smb = (u32)__cvta_generic_to_shared(sm2);
    const int wm = (warp >> 2) * 32;
    const int wn = (warp & 3) * 32;

    // per-thread load slots
    const int ra = tid >> 2, ca = tid & 3;                       // A: 64r x 4c
    const int rb0 = tid >> 4, cb0 = tid & 15;                    // B: 32r x 16c
    const int rb1 = (tid + 256) >> 4, cb1 = (tid + 256) & 15;
    const u32 sA = (u32)(ra * 80 + ca * 16);
    const u32 sB0 = (u32)(G2_ASZ + rb0 * 272 + cb0 * 16);
    const u32 sB1 = (u32)(G2_ASZ + rb1 * 272 + cb1 * 16);
    const char* gA = (const char*)g_aff + ((size_t)(m0 + ra) * NK + kt0 * 32 + ca * 8) * 2;
    const char* gB0 = (const char*)g_ckh + ((size_t)(kt0 * 32 + rb0) * D_DIM + n0 + cb0 * 8) * 2;
    const char* gB1 = (const char*)g_ckh + ((size_t)(kt0 * 32 + rb1) * D_DIM + n0 + cb1 * 8) * 2;

    float acc[2][4][4] = {};

    // prologue: stages 0,1,2
#pragma unroll
    for (int p = 0; p < 3; p++) {
        u32 Ab = smb + p * G2_STG;
        cp16(Ab + sA, gA);
        cp16(Ab + sB0, gB0); cp16(Ab + sB1, gB1);
        cp_commit();
        gA += 64; gB0 += 32768; gB1 += 32768;
    }

    const int NT = NK / NSPLIT / 32;  // 128
#pragma unroll 4
    for (int kt = 0; kt < NT; kt++) {
        cp_wait_2();
        __syncthreads();
        if (kt + 3 < NT) {
            u32 Ab = smb + ((kt + 3) & 3) * G2_STG;
            cp16(Ab + sA, gA);
            cp16(Ab + sB0, gB0); cp16(Ab + sB1, gB1);
            cp_commit();
            gA += 64; gB0 += 32768; gB1 += 32768;
        } else {
            cp_commit();
        }

        u32 Ab = smb + (kt & 3) * G2_STG;
        u32 Bb = Ab + G2_ASZ;
#pragma unroll
        for (int ks = 0; ks < 2; ks++) {
            u32 a[2][4];
            u32 b[2][4];
#pragma unroll
            for (int mi = 0; mi < 2; mi++) {
                ldsm_x4(a[mi], Ab + (wm + mi * 16 + (lane & 15)) * 80 + ks * 32 + (lane >> 4) * 16);
            }
#pragma unroll
            for (int j = 0; j < 2; j++) {
                int k = ks * 16 + (lane & 15);
                int n = wn + j * 16 + (lane >> 4) * 8;
                ldsm_x4_t(b[j], Bb + k * 272 + n * 2);
            }
#pragma unroll
            for (int mi = 0; mi < 2; mi++) {
#pragma unroll
                for (int j = 0; j < 2; j++) {
                    mma16816(acc[mi][j * 2 + 0], a[mi], b[j][0], b[j][1]);
                    mma16816(acc[mi][j * 2 + 1], a[mi], b[j][2], b[j][3]);
                }
            }
        }
    }

    // Epilogue: store fp32 partial
    float* part = g_part + (size_t)split * NB * D_DIM;
#pragma unroll
    for (int mi = 0; mi < 2; mi++) {
#pragma unroll
        for (int ni = 0; ni < 4; ni++) {
            int col = n0 + wn + ni * 8 + (lane & 3) * 2;
#pragma unroll
            for (int h = 0; h < 2; h++) {
                int row = m0 + wm + mi * 16 + (lane >> 2) + h * 8;
                float2 o;
                o.x = acc[mi][ni][2 * h + 0];
                o.y = acc[mi][ni][2 * h + 1];
                *(float2*)(part + (size_t)row * D_DIM + col) = o;
            }
        }
    }
}

// ---------------------------------------------------------------------------
// Reduce: out = q + ALPHA * sum_z part[z]
// ---------------------------------------------------------------------------
__global__ void __launch_bounds__(256) reduce_kernel(const float* __restrict__ Qorig,
                                                     float* __restrict__ Out) {
    size_t i = ((size_t)blockIdx.x * blockDim.x + threadIdx.x) * 4;
    float4 q = *(const float4*)(Qorig + i);
    float sx = 0.f, sy = 0.f, sz = 0.f, sw = 0.f;
#pragma unroll
    for (int z = 0; z < NSPLIT; z++) {
        float4 p = *(const float4*)(g_part + (size_t)z * NB * D_DIM + i);
        sx += p.x; sy += p.y; sz += p.z; sw += p.w;
    }
    float4 o;
    o.x = fmaf(ALPHA, sx, q.x);
    o.y = fmaf(ALPHA, sy, q.y);
    o.z = fmaf(ALPHA, sz, q.z);
    o.w = fmaf(ALPHA, sw, q.w);
    *(float4*)(Out + i) = o;
}

// ---------------------------------------------------------------------------
extern "C" void kernel_launch(void* const* d_in, const int* in_sizes, int n_in,
                              void* d_out, int out_size) {
    const float* qf;
    const float* sk;
    if (in_sizes[0] == NB * D_DIM) {
        qf = (const float*)d_in[0];
        sk = (const float*)d_in[1];
    } else {
        qf = (const float*)d_in[1];
        sk = (const float*)d_in[0];
    }

    // idempotent, called every time (no static state per harness rules)
    cudaFuncSetAttribute(gemm1_kernel, cudaFuncAttributeMaxDynamicSharedMemorySize,
                         G1_SMEM);
    cudaFuncSetAttribute(gemm2_kernel, cudaFuncAttributeMaxDynamicSharedMemorySize,
                         G2_SMEM);

    norm_rows<<<NK / 8, 256>>>(sk, NK, 1);
    norm_rows<<<NB / 8, 256>>>(qf, NB, 0);

    dim3 g1(NK / 128, NB / 128);           // (128, 32)
    gemm1_kernel<<<g1, 256, G1_SMEM>>>();

    dim3 g2(D_DIM / 128, NB / 64, NSPLIT); // (4, 64, 4)
    gemm2_kernel<<<g2, 256, G2_SMEM>>>();

    reduce_kernel<<<(NB * D_DIM) / (256 * 4), 256>>>(qf, (float*)d_out);
}

// round 17
// speedup vs baseline: 1.0488x; 1.0488x over previous
#include <cuda_runtime.h>
#include <cuda_bf16.h>
#include <stdint.h>
#include <cstdint>
#include <math.h>

typedef unsigned int u32;

#define D_DIM 512
#define NB 4096
#define NK 16384
#define BETA 5.5f
#define ALPHA 0.5f
#define NSPLIT 4

// bf16 scratch
__device__ __nv_bfloat16 g_qh[(size_t)NB * D_DIM];    // normalized queries (4 MB)
__device__ __nv_bfloat16 g_ckh[(size_t)NK * D_DIM];   // normalized keys    (16 MB)
__device__ __nv_bfloat16 g_aff[(size_t)NB * NK];      // affinity           (128 MB)
__device__ float g_part[(size_t)NSPLIT * NB * D_DIM]; // split-K partials   (32 MB)

// ---------------------------------------------------------------------------
// PTX helpers
// ---------------------------------------------------------------------------
__device__ __forceinline__ void cp16(u32 saddr, const void* g) {
    asm volatile("cp.async.cg.shared.global [%0], [%1], 16;\n" :: "r"(saddr), "l"(g));
}
__device__ __forceinline__ void cp_commit() { asm volatile("cp.async.commit_group;\n"); }
__device__ __forceinline__ void cp_wait_1() { asm volatile("cp.async.wait_group 1;\n"); }
__device__ __forceinline__ void cp_wait_2() { asm volatile("cp.async.wait_group 2;\n"); }
__device__ __forceinline__ void cp_wait_0() { asm volatile("cp.async.wait_group 0;\n"); }

__device__ __forceinline__ void ldsm_x4(u32* r, u32 addr) {
    asm volatile("ldmatrix.sync.aligned.m8n8.x4.shared.b16 {%0,%1,%2,%3}, [%4];\n"
        : "=r"(r[0]), "=r"(r[1]), "=r"(r[2]), "=r"(r[3]) : "r"(addr));
}
__device__ __forceinline__ void ldsm_x4_t(u32* r, u32 addr) {
    asm volatile("ldmatrix.sync.aligned.m8n8.x4.trans.shared.b16 {%0,%1,%2,%3}, [%4];\n"
        : "=r"(r[0]), "=r"(r[1]), "=r"(r[2]), "=r"(r[3]) : "r"(addr));
}
__device__ __forceinline__ void mma16816(float* c, const u32* a, u32 b0, u32 b1) {
    asm volatile(
        "mma.sync.aligned.m16n8k16.row.col.f32.bf16.bf16.f32 "
        "{%0,%1,%2,%3}, {%4,%5,%6,%7}, {%8,%9}, {%0,%1,%2,%3};\n"
        : "+f"(c[0]), "+f"(c[1]), "+f"(c[2]), "+f"(c[3])
        : "r"(a[0]), "r"(a[1]), "r"(a[2]), "r"(a[3]), "r"(b0), "r"(b1));
}

// ---------------------------------------------------------------------------
// Row L2-normalization -> bf16. One warp per 512-float row.
// ---------------------------------------------------------------------------
__global__ void __launch_bounds__(256) norm_rows(const float* __restrict__ src,
                                                 int rows, int dst_sel) {
    int w = (blockIdx.x * blockDim.x + threadIdx.x) >> 5;
    if (w >= rows) return;
    int lane = threadIdx.x & 31;
    __nv_bfloat16* dst = dst_sel ? g_ckh : g_qh;

    const float4* s = (const float4*)(src + (size_t)w * D_DIM);
    float4 v[4];
    float ss = 0.f;
#pragma unroll
    for (int i = 0; i < 4; i++) {
        v[i] = s[lane + 32 * i];
        ss += v[i].x * v[i].x + v[i].y * v[i].y + v[i].z * v[i].z + v[i].w * v[i].w;
    }
#pragma unroll
    for (int o = 16; o; o >>= 1) {
        ss += __shfl_xor_sync(0xffffffffu, ss, o);
    }
    float inv = 1.0f / fmaxf(sqrtf(ss), 1e-12f);

    uint2* d = (uint2*)(dst + (size_t)w * D_DIM);
#pragma unroll
    for (int i = 0; i < 4; i++) {
        __nv_bfloat162 lo = __floats2bfloat162_rn(v[i].x * inv, v[i].y * inv);
        __nv_bfloat162 hi = __floats2bfloat162_rn(v[i].z * inv, v[i].w * inv);
        uint2 u;
        u.x = *(u32*)&lo;
        u.y = *(u32*)&hi;
        d[lane + 32 * i] = u;
    }
}

// ---------------------------------------------------------------------------
// GEMM1 (R14 version — measured faster): 128x128x32 tiles, 8 warps,
// 4-stage cp.async ring, pointer-induction loads, one barrier per k-iter.
// ---------------------------------------------------------------------------
#define G1_ASZ 10240            // A (or B) bytes per stage
#define G1_STG (2 * G1_ASZ)
#define G1_SMEM (4 * G1_STG)    // 81920

__global__ void __launch_bounds__(256) gemm1_kernel() {
    extern __shared__ __align__(16) char sm1[];
    const int tid = threadIdx.x;
    const int warp = tid >> 5;
    const int lane = tid & 31;
    const int m0 = blockIdx.y * 128;
    const int n0 = blockIdx.x * 128;
    const int wm = (warp >> 2) * 64;
    const int wn = (warp & 3) * 32;
    const u32 smb = (u32)__cvta_generic_to_shared(sm1);

    const int r0 = tid >> 2, c0 = tid & 3;
    const int r1 = (tid + 256) >> 2, c1 = (tid + 256) & 3;
    const u32 sA0 = (u32)(r0 * 80 + c0 * 16);
    const u32 sA1 = (u32)(r1 * 80 + c1 * 16);
    const char* gA0 = (const char*)g_qh + ((size_t)(m0 + r0) * D_DIM + c0 * 8) * 2;
    const char* gA1 = (const char*)g_qh + ((size_t)(m0 + r1) * D_DIM + c1 * 8) * 2;
    const char* gB0 = (const char*)g_ckh + ((size_t)(n0 + r0) * D_DIM + c0 * 8) * 2;
    const char* gB1 = (const char*)g_ckh + ((size_t)(n0 + r1) * D_DIM + c1 * 8) * 2;

    float acc[4][4][4] = {};

    // prologue: stages 0,1,2
#pragma unroll
    for (int p = 0; p < 3; p++) {
        u32 Ab = smb + p * G1_STG;
        cp16(Ab + sA0, gA0); cp16(Ab + sA1, gA1);
        cp16(Ab + G1_ASZ + sA0, gB0); cp16(Ab + G1_ASZ + sA1, gB1);
        cp_commit();
        gA0 += 64; gA1 += 64; gB0 += 64; gB1 += 64;
    }

    const int NT = D_DIM / 32;  // 16
#pragma unroll 4
    for (int kt = 0; kt < NT; kt++) {
        cp_wait_2();
        __syncthreads();
        if (kt + 3 < NT) {
            u32 Ab = smb + ((kt + 3) & 3) * G1_STG;
            cp16(Ab + sA0, gA0); cp16(Ab + sA1, gA1);
            cp16(Ab + G1_ASZ + sA0, gB0); cp16(Ab + G1_ASZ + sA1, gB1);
            cp_commit();
            gA0 += 64; gA1 += 64; gB0 += 64; gB1 += 64;
        } else {
            cp_commit();   // empty group keeps wait-count arithmetic uniform
        }

        u32 Ab = smb + (kt & 3) * G1_STG;
        u32 Bb = Ab + G1_ASZ;
#pragma unroll
        for (int ks = 0; ks < 2; ks++) {
            u32 a[4][4];
            u32 b[2][4];
#pragma unroll
            for (int mi = 0; mi < 4; mi++) {
                ldsm_x4(a[mi], Ab + (wm + mi * 16 + (lane & 15)) * 80 + ks * 32 + (lane >> 4) * 16);
            }
#pragma unroll
            for (int j = 0; j < 2; j++) {
                ldsm_x4(b[j], Bb + (wn + j * 16 + (lane & 15)) * 80 + ks * 32 + (lane >> 4) * 16);
            }
#pragma unroll
            for (int mi = 0; mi < 4; mi++) {
#pragma unroll
                for (int j = 0; j < 2; j++) {
                    mma16816(acc[mi][j * 2 + 0], a[mi], b[j][0], b[j][2]);
                    mma16816(acc[mi][j * 2 + 1], a[mi], b[j][1], b[j][3]);
                }
            }
        }
    }

    // Epilogue: exp + bf16 store
#pragma unroll
    for (int mi = 0; mi < 4; mi++) {
#pragma unroll
        for (int ni = 0; ni < 4; ni++) {
            int col = n0 + wn + ni * 8 + (lane & 3) * 2;
#pragma unroll
            for (int h = 0; h < 2; h++) {
                int row = m0 + wm + mi * 16 + (lane >> 2) + h * 8;
                float e0 = __expf(fmaf(BETA, acc[mi][ni][2 * h + 0], -BETA));
                float e1 = __expf(fmaf(BETA, acc[mi][ni][2 * h + 1], -BETA));
                __nv_bfloat162 v = __floats2bfloat162_rn(e0, e1);
                *(u32*)(&g_aff[(size_t)row * NK + col]) = *(u32*)&v;
            }
        }
    }
}

// ---------------------------------------------------------------------------
// GEMM2 (R13 version — measured 218us): split-K x4, 64x128 tiles, 8 warps,
// 3-stage pipeline, two barriers per k-iter, static smem, launch_bounds(256,4).
// ---------------------------------------------------------------------------
#define G2_ASZ (64 * 80)    // 5120
#define G2_BSZ (32 * 272)   // 8704
#define G2_STG (G2_ASZ + G2_BSZ)

__device__ __forceinline__ void g2_load(u32 smb, int s, int m0, int n0,
                                        int kt, int tid) {
    u32 Ab = smb + s * G2_STG;
    u32 Bb = Ab + G2_ASZ;
    {   // A: 64 rows x 4 chunks = 256 chunks
        int row = tid >> 2;
        int c = tid & 3;
        const char* ga = (const char*)g_aff + ((size_t)(m0 + row) * NK + kt * 32 + c * 8) * 2;
        cp16(Ab + row * 80 + c * 16, ga);
    }
#pragma unroll
    for (int p = 0; p < 2; p++) {  // B: 32 rows x 16 chunks = 512 chunks
        int chunk = tid + p * 256;
        int row = chunk >> 4;
        int c = chunk & 15;
        const char* gb = (const char*)g_ckh + ((size_t)(kt * 32 + row) * D_DIM + n0 + c * 8) * 2;
        cp16(Bb + row * 272 + c * 16, gb);
    }
    cp_commit();
}

__global__ void __launch_bounds__(256, 4) gemm2_kernel() {
    __shared__ __align__(16) char sm[3 * G2_STG];  // 41472 bytes
    const int tid = threadIdx.x;
    const int warp = tid >> 5;
    const int lane = tid & 31;
    const int m0 = blockIdx.y * 64;
    const int n0 = blockIdx.x * 128;
    const int split = blockIdx.z;
    const int kt0 = split * (NK / NSPLIT / 32);
    const u32 smb = (u32)__cvta_generic_to_shared(sm);
    const int wm = (warp >> 2) * 32;
    const int wn = (warp & 3) * 32;

    float acc[2][4][4] = {};

    g2_load(smb, 0, m0, n0, kt0 + 0, tid);
    g2_load(smb, 1, m0, n0, kt0 + 1, tid);

    const int NT = NK / NSPLIT / 32;  // 128
    for (int kt = 0; kt < NT; kt++) {
        cp_wait_1();
        __syncthreads();
        if (kt + 2 < NT) {
            int s = kt + 2;
            g2_load(smb, s - (s / 3) * 3, m0, n0, kt0 + s, tid);
        }

        int cs = kt - (kt / 3) * 3;
        u32 Ab = smb + cs * G2_STG;
        u32 Bb = Ab + G2_ASZ;
#pragma unroll
        for (int ks = 0; ks < 2; ks++) {
            u32 a[2][4];
            u32 b[2][4];
#pragma unroll
            for (int mi = 0; mi < 2; mi++) {
                ldsm_x4(a[mi], Ab + (wm + mi * 16 + (lane & 15)) * 80 + ks * 32 + (lane >> 4) * 16);
            }
#pragma unroll
            for (int j = 0; j < 2; j++) {
                int k = ks * 16 + (lane & 15);
                int n = wn + j * 16 + (lane >> 4) * 8;
                ldsm_x4_t(b[j], Bb + k * 272 + n * 2);
            }
#pragma unroll
            for (int mi = 0; mi < 2; mi++) {
#pragma unroll
                for (int j = 0; j < 2; j++) {
                    mma16816(acc[mi][j * 2 + 0], a[mi], b[j][0], b[j][1]);
                    mma16816(acc[mi][j * 2 + 1], a[mi], b[j][2], b[j][3]);
                }
            }
        }
        __syncthreads();
    }

    // Epilogue: store fp32 partial
    float* part = g_part + (size_t)split * NB * D_DIM;
#pragma unroll
    for (int mi = 0; mi < 2; mi++) {
#pragma unroll
        for (int ni = 0; ni < 4; ni++) {
            int col = n0 + wn + ni * 8 + (lane & 3) * 2;
#pragma unroll
            for (int h = 0; h < 2; h++) {
                int row = m0 + wm + mi * 16 + (lane >> 2) + h * 8;
                float2 o;
                o.x = acc[mi][ni][2 * h + 0];
                o.y = acc[mi][ni][2 * h + 1];
                *(float2*)(part + (size_t)row * D_DIM + col) = o;
            }
        }
    }
}

// ---------------------------------------------------------------------------
// Reduce: out = q + ALPHA * sum_z part[z]
// ---------------------------------------------------------------------------
__global__ void __launch_bounds__(256) reduce_kernel(const float* __restrict__ Qorig,
                                                     float* __restrict__ Out) {
    size_t i = ((size_t)blockIdx.x * blockDim.x + threadIdx.x) * 4;
    float4 q = *(const float4*)(Qorig + i);
    float sx = 0.f, sy = 0.f, sz = 0.f, sw = 0.f;
#pragma unroll
    for (int z = 0; z < NSPLIT; z++) {
        float4 p = *(const float4*)(g_part + (size_t)z * NB * D_DIM + i);
        sx += p.x; sy += p.y; sz += p.z; sw += p.w;
    }
    float4 o;
    o.x = fmaf(ALPHA, sx, q.x);
    o.y = fmaf(ALPHA, sy, q.y);
    o.z = fmaf(ALPHA, sz, q.z);
    o.w = fmaf(ALPHA, sw, q.w);
    *(float4*)(Out + i) = o;
}

// ---------------------------------------------------------------------------
extern "C" void kernel_launch(void* const* d_in, const int* in_sizes, int n_in,
                              void* d_out, int out_size) {
    const float* qf;
    const float* sk;
    if (in_sizes[0] == NB * D_DIM) {
        qf = (const float*)d_in[0];
        sk = (const float*)d_in[1];
    } else {
        qf = (const float*)d_in[1];
        sk = (const float*)d_in[0];
    }

    cudaFuncSetAttribute(gemm1_kernel, cudaFuncAttributeMaxDynamicSharedMemorySize,
                         G1_SMEM);

    norm_rows<<<NK / 8, 256>>>(sk, NK, 1);
    norm_rows<<<NB / 8, 256>>>(qf, NB, 0);

    dim3 g1(NK / 128, NB / 128);           // (128, 32)
    gemm1_kernel<<<g1, 256, G1_SMEM>>>();

    dim3 g2(D_DIM / 128, NB / 64, NSPLIT); // (4, 64, 4)
    gemm2_kernel<<<g2, 256>>>();

    reduce_kernel<<<(NB * D_DIM) / (256 * 4), 256>>>(qf, (float*)d_out);
}